// round 13
// baseline (speedup 1.0000x reference)
#include <cuda_runtime.h>

// Problem constants (fixed by reference hparams)
#define BB     32          // batch
#define NSEG   108         // MAX_NUM_SEG
#define NTOT   3456        // BB*NSEG
#define SS     64          // candidates per segment
#define TX     2560        // MAX_LEN_PAD
#define D4     20          // feature dim / 4 (float4 units)
#define MINSEG 19
#define OUTROWS (BB * TX)  // 81920 output rows

// Scratch (no allocations allowed -> __device__ globals)
__device__ int4 g_seginfo[NTOT];    // {local_base, cnt, off, scale_bits}
__device__ int  g_btot[BB];         // per-batch count totals
__device__ int2 g_meta2[OUTROWS];   // per OUTPUT row: {src_row, lam} or {-1,0}

// ---------------------------------------------------------------------------
// shfl exclusive warp scan; returns exclusive prefix, sets warp total
// ---------------------------------------------------------------------------
__device__ __forceinline__ int warp_excl(int v, int lane, int& tot) {
    int x = v;
#pragma unroll
    for (int o = 1; o < 32; o <<= 1) {
        int y = __shfl_up_sync(0xffffffffu, x, o);
        if (lane >= o) x += y;
    }
    tot = __shfl_sync(0xffffffffu, x, 31);
    return x - v;
}

// Masked count for one segment: #{ s in [0,64) : floor(rn(s/scale)) < L }.
// Estimate seed + exact __fdiv_rn verification -> bit-exact vs reference.
__device__ __forceinline__ int seg_cnt(int len, int lseq, int off, float scale) {
    const int L = min(len - 1, lseq - 1 - off);
    if (L <= 0) return 0;
    const float Lf = (float)L;
    int s = (int)(Lf * scale);             // seed near the boundary
    if (s > 63) s = 63;
    while (s > 0 && !(floorf(__fdiv_rn((float)s, scale)) < Lf)) s--;
    while (s < 63 && (floorf(__fdiv_rn((float)(s + 1), scale)) < Lf)) s++;
    return s + 1;                          // cond(0) true since L>0
}

// ---------------------------------------------------------------------------
// Kernel 1: one WARP per batch (32 blocks x 32 threads), zero barriers.
// Triggers PDL completion at entry so k_rowmeta's dispatch overlaps this body.
// ---------------------------------------------------------------------------
__global__ void __launch_bounds__(32) k_seg(const int* __restrict__ len_seq,
                                            const float* __restrict__ scales_u,
                                            const int* __restrict__ len_seg_raw) {
    cudaTriggerProgrammaticLaunchCompletion();   // let consumers start dispatch

    const int b = blockIdx.x;
    const int lane = threadIdx.x;
    const bool act = lane < NSEG / 4;      // 27 active lanes

    int4 lr = make_int4(-MINSEG, -MINSEG, -MINSEG, -MINSEG);
    float4 sc = make_float4(0.5f, 0.5f, 0.5f, 0.5f);
    const int vidx = b * (NSEG / 4) + lane;
    if (act) {
        lr = ((const int4*)len_seg_raw)[vidx];
        sc = ((const float4*)scales_u)[vidx];
    }
    const int lseq = len_seq[b];

    const int l0 = lr.x + MINSEG, l1 = lr.y + MINSEG;
    const int l2 = lr.z + MINSEG, l3 = lr.w + MINSEG;
    const float s0 = sc.x + 0.5f, s1 = sc.y + 0.5f;
    const float s2 = sc.z + 0.5f, s3 = sc.w + 0.5f;

    // scan #1: len_seg -> offsets
    int tot;
    const int ex = warp_excl(l0 + l1 + l2 + l3, lane, tot);
    const int o0 = ex, o1 = ex + l0, o2 = o1 + l1, o3 = o2 + l2;

    // counts (ILP across 4 segments)
    const int c0 = seg_cnt(l0, lseq, o0, s0);
    const int c1 = seg_cnt(l1, lseq, o1, s1);
    const int c2 = seg_cnt(l2, lseq, o2, s2);
    const int c3 = seg_cnt(l3, lseq, o3, s3);

    // scan #2: counts -> local bases + batch total
    int ctot;
    const int cex = warp_excl(c0 + c1 + c2 + c3, lane, ctot);

    if (act) {
        const int n0 = b * NSEG + lane * 4;
        g_seginfo[n0 + 0] = make_int4(cex,                c0, o0, __float_as_int(s0));
        g_seginfo[n0 + 1] = make_int4(cex + c0,           c1, o1, __float_as_int(s1));
        g_seginfo[n0 + 2] = make_int4(cex + c0 + c1,      c2, o2, __float_as_int(s2));
        g_seginfo[n0 + 3] = make_int4(cex + c0 + c1 + c2, c3, o3, __float_as_int(s3));
    }
    if (lane == 0) g_btot[b] = ctot;
}

// ---------------------------------------------------------------------------
// Kernel 2: scatter metadata DIRECTLY into output-row order.
//   meta2[b_out*TX + t] = {src_row, lam}  for valid rows (t < rows)
//   meta2[b_out*TX + t] = {-1, 0}         for padding   (t in [rows, TX))
// PDL: launched with PSS; gridsync before touching k_seg's outputs; triggers
// at entry so k_gather's dispatch overlaps this body.
// ---------------------------------------------------------------------------
__global__ void __launch_bounds__(256) k_rowmeta() {
    cudaTriggerProgrammaticLaunchCompletion();   // let gather start dispatch

    __shared__ int sbb[BB];
    __shared__ int s_rows;

    const int tid = threadIdx.x;
    const int lane = tid & 31;
    const int n = blockIdx.x * 8 + (tid >> 5);   // this warp's segment

    cudaGridDependencySynchronize();             // wait: k_seg outputs visible

    if (tid < 32) {
        int t;
        int ex = warp_excl(g_btot[tid], tid, t);
        sbb[tid] = ex;
        if (tid == 31) s_rows = t / BB;
    }
    __syncthreads();
    const int rows = s_rows;

    // ---- valid-row scatter: 8 warps -> 8 segments per block ----
    const int4 si = g_seginfo[n];          // {local_base, cnt, off, scale_bits}
    const int cnt = si.y;
    if (cnt > 0 && rows > 0) {
        const int base  = sbb[n / NSEG] + si.x;   // absolute compacted base
        const int off   = si.z;
        const float scale = __int_as_float(si.w);
        const int bTX   = (n / NSEG) * TX;        // SOURCE batch row base

        for (int s = lane; s < cnt; s += 32) {    // cnt <= 64 -> <= 2 iters
            const float v  = __fdiv_rn((float)s, scale);
            const float fl = floorf(v);
            const float lam = v - fl;
            int i = (int)fl + off;                // exact small ints
            if (i > TX - 2) i = TX - 2;
            if (i < 0) i = 0;

            const int p = base + s;
            const int b_out = p / rows;           // output batch of position p
            const int t = p - b_out * rows;
            if (t < TX && b_out < BB)             // rows>TX or tail overflow
                g_meta2[b_out * TX + t] = make_int2(bTX + i, __float_as_int(lam));
        }
    }

    // ---- padding fill: grid-stride over the complement region ----
    const int padh = (rows < TX) ? (TX - rows) : 0;   // padding per batch
    const int padtot = BB * padh;
    for (int j = blockIdx.x * 256 + tid; j < padtot; j += (NTOT / 8) * 256) {
        const int b_out = j / padh;
        const int t = rows + (j - b_out * padh);
        g_meta2[b_out * TX + t] = make_int2(-1, 0);
    }
}

// ---------------------------------------------------------------------------
// Kernel 3: flat gather, ILP=4. Each thread produces FOUR output float4s.
// All 4 meta loads issue back-to-back (independent), then up to 8 x loads —
// ~12 loads in flight per thread at the same occupancy. Index math runs
// BEFORE the PDL gridsync so it overlaps k_rowmeta's tail. Stores perfectly
// coalesced (quads strided by 256 within the block).
// ---------------------------------------------------------------------------
__global__ void __launch_bounds__(256) k_gather(const float* __restrict__ x,
                                                float* __restrict__ out) {
    const int base = blockIdx.x * 1024 + threadIdx.x;   // quads: base + k*256

    int row[4], d4[4];
#pragma unroll
    for (int k = 0; k < 4; k++) {
        const int g = base + k * 256;
        row[k] = g / D4;
        d4[k]  = g - row[k] * D4;
    }

    cudaGridDependencySynchronize();             // wait: g_meta2 visible

    int2 m[4];
#pragma unroll
    for (int k = 0; k < 4; k++) m[k] = g_meta2[row[k]];   // 4 independent loads

    const float4* __restrict__ x4 = (const float4*)x;
    float4 a[4], c[4];
#pragma unroll
    for (int k = 0; k < 4; k++) {
        if (m[k].x >= 0) {
            const int sb = m[k].x * D4 + d4[k];
            a[k] = x4[sb];
            c[k] = x4[sb + D4];
        }
    }

    float4* __restrict__ o4 = (float4*)out;
#pragma unroll
    for (int k = 0; k < 4; k++) {
        float4 r = make_float4(0.f, 0.f, 0.f, 0.f);
        if (m[k].x >= 0) {
            const float lam = __int_as_float(m[k].y), om = 1.0f - lam;
            r.x = om * a[k].x + lam * c[k].x;
            r.y = om * a[k].y + lam * c[k].y;
            r.z = om * a[k].z + lam * c[k].z;
            r.w = om * a[k].w + lam * c[k].w;
        }
        o4[base + k * 256] = r;
    }
}

// ---------------------------------------------------------------------------
extern "C" void kernel_launch(void* const* d_in, const int* in_sizes, int n_in,
                              void* d_out, int out_size) {
    const float* x           = (const float*)d_in[0];  // (32, 2560, 80) f32
    const int*   len_seq     = (const int*)d_in[1];    // (32,) i32
    const float* scales_u    = (const float*)d_in[2];  // (3456,) f32
    const int*   len_seg_raw = (const int*)d_in[3];    // (3456,) i32
    float*       out         = (float*)d_out;          // (32, 2560, 80) f32

    // node 1: plain launch
    k_seg<<<BB, 32>>>(len_seq, scales_u, len_seg_raw);

    // PDL attribute: dependent grid may begin dispatch when producer triggers
    cudaLaunchAttribute attr[1];
    attr[0].id = cudaLaunchAttributeProgrammaticStreamSerialization;
    attr[0].val.programmaticStreamSerializationAllowed = 1;

    // node 2: k_rowmeta (PDL consumer of k_seg, producer for k_gather)
    {
        cudaLaunchConfig_t cfg = {};
        cfg.gridDim = dim3(NTOT / 8);
        cfg.blockDim = dim3(256);
        cfg.dynamicSmemBytes = 0;
        cfg.stream = 0;                 // legacy default stream (same as <<<>>>)
        cfg.attrs = attr;
        cfg.numAttrs = 1;
        cudaLaunchKernelEx(&cfg, k_rowmeta);
    }

    // node 3: k_gather (PDL consumer of k_rowmeta)
    {
        cudaLaunchConfig_t cfg = {};
        cfg.gridDim = dim3((BB * TX * D4) / 1024);
        cfg.blockDim = dim3(256);
        cfg.dynamicSmemBytes = 0;
        cfg.stream = 0;
        cfg.attrs = attr;
        cfg.numAttrs = 1;
        cudaLaunchKernelEx(&cfg, k_gather, x, out);
    }
}

// round 14
// speedup vs baseline: 1.0173x; 1.0173x over previous
#include <cuda_runtime.h>

// Problem constants (fixed by reference hparams)
#define BB     32          // batch
#define NSEG   108         // MAX_NUM_SEG
#define NTOT   3456        // BB*NSEG
#define SS     64          // candidates per segment
#define TX     2560        // MAX_LEN_PAD
#define D4     20          // feature dim / 4 (float4 units)
#define MINSEG 19
#define OUTROWS (BB * TX)  // 81920 output rows

// Scratch (no allocations allowed -> __device__ globals)
__device__ int4 g_seginfo[NTOT];    // {local_base, cnt, off, scale_bits}
__device__ int  g_btot[BB];         // per-batch count totals
__device__ int2 g_bbr[BB];          // per batch: {absolute base, rows}
__device__ unsigned g_ctr = 0;      // last-block-done counter (wraps -> replay-safe)
__device__ int2 g_meta2[OUTROWS];   // per OUTPUT row: {src_row, lam} or {-1,0}

// ---------------------------------------------------------------------------
// shfl exclusive warp scan; returns exclusive prefix, sets warp total
// ---------------------------------------------------------------------------
__device__ __forceinline__ int warp_excl(int v, int lane, int& tot) {
    int x = v;
#pragma unroll
    for (int o = 1; o < 32; o <<= 1) {
        int y = __shfl_up_sync(0xffffffffu, x, o);
        if (lane >= o) x += y;
    }
    tot = __shfl_sync(0xffffffffu, x, 31);
    return x - v;
}

// Masked count for one segment: #{ s in [0,64) : floor(rn(s/scale)) < L }.
// Estimate seed + exact __fdiv_rn verification -> bit-exact vs reference.
__device__ __forceinline__ int seg_cnt(int len, int lseq, int off, float scale) {
    const int L = min(len - 1, lseq - 1 - off);
    if (L <= 0) return 0;
    const float Lf = (float)L;
    int s = (int)(Lf * scale);             // seed near the boundary
    if (s > 63) s = 63;
    while (s > 0 && !(floorf(__fdiv_rn((float)s, scale)) < Lf)) s--;
    while (s < 63 && (floorf(__fdiv_rn((float)(s + 1), scale)) < Lf)) s++;
    return s + 1;                          // cond(0) true since L>0
}

// ---------------------------------------------------------------------------
// Kernel 1: one WARP per batch (32 blocks x 32 threads), zero barriers.
// Last-block-done epilogue computes the cross-batch scan ONCE (absolute batch
// bases + rows), so k_rowmeta needs no prologue at all. atomicInc wraps the
// counter back to 0 every run -> deterministic across graph replays.
// ---------------------------------------------------------------------------
__global__ void __launch_bounds__(32) k_seg(const int* __restrict__ len_seq,
                                            const float* __restrict__ scales_u,
                                            const int* __restrict__ len_seg_raw) {
    cudaTriggerProgrammaticLaunchCompletion();   // let consumers start dispatch

    const int b = blockIdx.x;
    const int lane = threadIdx.x;
    const bool act = lane < NSEG / 4;      // 27 active lanes

    int4 lr = make_int4(-MINSEG, -MINSEG, -MINSEG, -MINSEG);
    float4 sc = make_float4(0.5f, 0.5f, 0.5f, 0.5f);
    const int vidx = b * (NSEG / 4) + lane;
    if (act) {
        lr = ((const int4*)len_seg_raw)[vidx];
        sc = ((const float4*)scales_u)[vidx];
    }
    const int lseq = len_seq[b];

    const int l0 = lr.x + MINSEG, l1 = lr.y + MINSEG;
    const int l2 = lr.z + MINSEG, l3 = lr.w + MINSEG;
    const float s0 = sc.x + 0.5f, s1 = sc.y + 0.5f;
    const float s2 = sc.z + 0.5f, s3 = sc.w + 0.5f;

    // scan #1: len_seg -> offsets
    int tot;
    const int ex = warp_excl(l0 + l1 + l2 + l3, lane, tot);
    const int o0 = ex, o1 = ex + l0, o2 = o1 + l1, o3 = o2 + l2;

    // counts (ILP across 4 segments)
    const int c0 = seg_cnt(l0, lseq, o0, s0);
    const int c1 = seg_cnt(l1, lseq, o1, s1);
    const int c2 = seg_cnt(l2, lseq, o2, s2);
    const int c3 = seg_cnt(l3, lseq, o3, s3);

    // scan #2: counts -> local bases + batch total
    int ctot;
    const int cex = warp_excl(c0 + c1 + c2 + c3, lane, ctot);

    if (act) {
        const int n0 = b * NSEG + lane * 4;
        g_seginfo[n0 + 0] = make_int4(cex,                c0, o0, __float_as_int(s0));
        g_seginfo[n0 + 1] = make_int4(cex + c0,           c1, o1, __float_as_int(s1));
        g_seginfo[n0 + 2] = make_int4(cex + c0 + c1,      c2, o2, __float_as_int(s2));
        g_seginfo[n0 + 3] = make_int4(cex + c0 + c1 + c2, c3, o3, __float_as_int(s3));
    }
    if (lane == 0) g_btot[b] = ctot;

    // ---- last-block-done: cross-batch scan, once ----
    __threadfence();                      // publish g_btot before the inc
    unsigned old = 0;
    if (lane == 0) old = atomicInc(&g_ctr, BB - 1);   // wraps to 0 -> replay-safe
    old = __shfl_sync(0xffffffffu, old, 0);
    if (old == BB - 1) {                  // exactly one block per run
        __threadfence();
        const int bt = atomicAdd(&g_btot[lane], 0);   // L2-coherent read
        int gtot;
        const int gex = warp_excl(bt, lane, gtot);
        g_bbr[lane] = make_int2(gex, gtot / BB);      // {abs base, rows}
    }
}

// ---------------------------------------------------------------------------
// Kernel 2: scatter metadata DIRECTLY into output-row order.
//   meta2[b_out*TX + t] = {src_row, lam}  for valid rows (t < rows)
//   meta2[b_out*TX + t] = {-1, 0}         for padding   (t in [rows, TX))
// No prologue: just two independent loads (seginfo, bbr). No smem/barriers.
// PDL: gridsync before touching k_seg outputs; triggers at entry.
// ---------------------------------------------------------------------------
__global__ void __launch_bounds__(256) k_rowmeta() {
    cudaTriggerProgrammaticLaunchCompletion();   // let gather start dispatch

    const int tid = threadIdx.x;
    const int lane = tid & 31;
    const int n = blockIdx.x * 8 + (tid >> 5);   // this warp's segment
    const int bsrc = n / NSEG;                   // source batch

    cudaGridDependencySynchronize();             // wait: k_seg outputs visible

    const int4 si  = g_seginfo[n];       // {local_base, cnt, off, scale_bits}
    const int2 bbr = g_bbr[bsrc];        // {abs batch base, rows}
    const int rows = bbr.y;

    const int cnt = si.y;
    if (cnt > 0 && rows > 0) {
        const int base  = bbr.x + si.x;           // absolute compacted base
        const int off   = si.z;
        const float scale = __int_as_float(si.w);
        const int bTX   = bsrc * TX;              // SOURCE batch row base

        for (int s = lane; s < cnt; s += 32) {    // cnt <= 64 -> <= 2 iters
            const float v  = __fdiv_rn((float)s, scale);
            const float fl = floorf(v);
            const float lam = v - fl;
            int i = (int)fl + off;                // exact small ints
            if (i > TX - 2) i = TX - 2;
            if (i < 0) i = 0;

            const int p = base + s;
            const int b_out = p / rows;           // output batch of position p
            const int t = p - b_out * rows;
            if (t < TX && b_out < BB)             // rows>TX or tail overflow
                g_meta2[b_out * TX + t] = make_int2(bTX + i, __float_as_int(lam));
        }
    }

    // ---- padding fill: grid-stride over the complement region ----
    const int padh = (rows < TX) ? (TX - rows) : 0;   // padding per batch
    const int padtot = BB * padh;
    for (int j = blockIdx.x * 256 + tid; j < padtot; j += (NTOT / 8) * 256) {
        const int b_out = j / padh;
        const int t = rows + (j - b_out * padh);
        g_meta2[b_out * TX + t] = make_int2(-1, 0);
    }
}

// ---------------------------------------------------------------------------
// Kernel 3: flat gather, ILP=2 (the R12 winner, unchanged). Index math runs
// BEFORE the PDL gridsync so it overlaps k_rowmeta's tail.
// ---------------------------------------------------------------------------
__global__ void __launch_bounds__(256) k_gather(const float* __restrict__ x,
                                                float* __restrict__ out) {
    const int g0 = blockIdx.x * 512 + threadIdx.x;   // two quads: g0, g0+256
    const int g1 = g0 + 256;

    const int row0 = g0 / D4, d40 = g0 - row0 * D4;
    const int row1 = g1 / D4, d41 = g1 - row1 * D4;

    cudaGridDependencySynchronize();             // wait: g_meta2 visible

    const int2 m0 = g_meta2[row0];                    // independent loads
    const int2 m1 = g_meta2[row1];

    const float4* __restrict__ x4 = (const float4*)x;
    float4 r0 = make_float4(0.f, 0.f, 0.f, 0.f);
    float4 r1 = make_float4(0.f, 0.f, 0.f, 0.f);

    if (m0.x >= 0) {
        const int sb = m0.x * D4 + d40;
        const float4 a = x4[sb];
        const float4 c = x4[sb + D4];
        const float lam = __int_as_float(m0.y), om = 1.0f - lam;
        r0.x = om * a.x + lam * c.x;  r0.y = om * a.y + lam * c.y;
        r0.z = om * a.z + lam * c.z;  r0.w = om * a.w + lam * c.w;
    }
    if (m1.x >= 0) {
        const int sb = m1.x * D4 + d41;
        const float4 a = x4[sb];
        const float4 c = x4[sb + D4];
        const float lam = __int_as_float(m1.y), om = 1.0f - lam;
        r1.x = om * a.x + lam * c.x;  r1.y = om * a.y + lam * c.y;
        r1.z = om * a.z + lam * c.z;  r1.w = om * a.w + lam * c.w;
    }

    float4* __restrict__ o4 = (float4*)out;
    o4[g0] = r0;
    o4[g1] = r1;
}

// ---------------------------------------------------------------------------
extern "C" void kernel_launch(void* const* d_in, const int* in_sizes, int n_in,
                              void* d_out, int out_size) {
    const float* x           = (const float*)d_in[0];  // (32, 2560, 80) f32
    const int*   len_seq     = (const int*)d_in[1];    // (32,) i32
    const float* scales_u    = (const float*)d_in[2];  // (3456,) f32
    const int*   len_seg_raw = (const int*)d_in[3];    // (3456,) i32
    float*       out         = (float*)d_out;          // (32, 2560, 80) f32

    // node 1: plain launch
    k_seg<<<BB, 32>>>(len_seq, scales_u, len_seg_raw);

    // PDL attribute: dependent grid may begin dispatch when producer triggers
    cudaLaunchAttribute attr[1];
    attr[0].id = cudaLaunchAttributeProgrammaticStreamSerialization;
    attr[0].val.programmaticStreamSerializationAllowed = 1;

    // node 2: k_rowmeta (PDL consumer of k_seg, producer for k_gather)
    {
        cudaLaunchConfig_t cfg = {};
        cfg.gridDim = dim3(NTOT / 8);
        cfg.blockDim = dim3(256);
        cfg.dynamicSmemBytes = 0;
        cfg.stream = 0;                 // legacy default stream (same as <<<>>>)
        cfg.attrs = attr;
        cfg.numAttrs = 1;
        cudaLaunchKernelEx(&cfg, k_rowmeta);
    }

    // node 3: k_gather (PDL consumer of k_rowmeta)
    {
        cudaLaunchConfig_t cfg = {};
        cfg.gridDim = dim3((BB * TX * D4) / 512);
        cfg.blockDim = dim3(256);
        cfg.dynamicSmemBytes = 0;
        cfg.stream = 0;
        cfg.attrs = attr;
        cfg.numAttrs = 1;
        cudaLaunchKernelEx(&cfg, k_gather, x, out);
    }
}

// round 15
// speedup vs baseline: 1.1544x; 1.1348x over previous
#include <cuda_runtime.h>

// Problem constants (fixed by reference hparams)
#define BB     32          // batch
#define NSEG   108         // MAX_NUM_SEG
#define NTOT   3456        // BB*NSEG
#define SS     64          // candidates per segment
#define TX     2560        // MAX_LEN_PAD
#define D4     20          // feature dim / 4 (float4 units)
#define MINSEG 19
#define OUTROWS (BB * TX)  // 81920 output rows

// Scratch (no allocations allowed -> __device__ globals)
__device__ int4 g_seginfo[NTOT];    // {local_base, cnt, off, scale_bits}
__device__ int  g_btot[BB];         // per-batch count totals
__device__ int2 g_meta2[OUTROWS];   // per OUTPUT row: {src_row, lam} or {-1,0}

// ---------------------------------------------------------------------------
// shfl exclusive warp scan; returns exclusive prefix, sets warp total
// ---------------------------------------------------------------------------
__device__ __forceinline__ int warp_excl(int v, int lane, int& tot) {
    int x = v;
#pragma unroll
    for (int o = 1; o < 32; o <<= 1) {
        int y = __shfl_up_sync(0xffffffffu, x, o);
        if (lane >= o) x += y;
    }
    tot = __shfl_sync(0xffffffffu, x, 31);
    return x - v;
}

// Masked count for one segment: #{ s in [0,64) : floor(rn(s/scale)) < L }.
// Estimate seed + exact __fdiv_rn verification -> bit-exact vs reference.
__device__ __forceinline__ int seg_cnt(int len, int lseq, int off, float scale) {
    const int L = min(len - 1, lseq - 1 - off);
    if (L <= 0) return 0;
    const float Lf = (float)L;
    int s = (int)(Lf * scale);             // seed near the boundary
    if (s > 63) s = 63;
    while (s > 0 && !(floorf(__fdiv_rn((float)s, scale)) < Lf)) s--;
    while (s < 63 && (floorf(__fdiv_rn((float)(s + 1), scale)) < Lf)) s++;
    return s + 1;                          // cond(0) true since L>0
}

// ---------------------------------------------------------------------------
// Kernel 1: one WARP per batch (32 blocks x 32 threads), zero barriers.
// Triggers PDL completion at entry so k_rowmeta's dispatch overlaps this body.
// (R12's exact version - no epilogue; producer stays as short as possible.)
// ---------------------------------------------------------------------------
__global__ void __launch_bounds__(32) k_seg(const int* __restrict__ len_seq,
                                            const float* __restrict__ scales_u,
                                            const int* __restrict__ len_seg_raw) {
    cudaTriggerProgrammaticLaunchCompletion();   // let consumers start dispatch

    const int b = blockIdx.x;
    const int lane = threadIdx.x;
    const bool act = lane < NSEG / 4;      // 27 active lanes

    int4 lr = make_int4(-MINSEG, -MINSEG, -MINSEG, -MINSEG);
    float4 sc = make_float4(0.5f, 0.5f, 0.5f, 0.5f);
    const int vidx = b * (NSEG / 4) + lane;
    if (act) {
        lr = ((const int4*)len_seg_raw)[vidx];
        sc = ((const float4*)scales_u)[vidx];
    }
    const int lseq = len_seq[b];

    const int l0 = lr.x + MINSEG, l1 = lr.y + MINSEG;
    const int l2 = lr.z + MINSEG, l3 = lr.w + MINSEG;
    const float s0 = sc.x + 0.5f, s1 = sc.y + 0.5f;
    const float s2 = sc.z + 0.5f, s3 = sc.w + 0.5f;

    // scan #1: len_seg -> offsets
    int tot;
    const int ex = warp_excl(l0 + l1 + l2 + l3, lane, tot);
    const int o0 = ex, o1 = ex + l0, o2 = o1 + l1, o3 = o2 + l2;

    // counts (ILP across 4 segments)
    const int c0 = seg_cnt(l0, lseq, o0, s0);
    const int c1 = seg_cnt(l1, lseq, o1, s1);
    const int c2 = seg_cnt(l2, lseq, o2, s2);
    const int c3 = seg_cnt(l3, lseq, o3, s3);

    // scan #2: counts -> local bases + batch total
    int ctot;
    const int cex = warp_excl(c0 + c1 + c2 + c3, lane, ctot);

    if (act) {
        const int n0 = b * NSEG + lane * 4;
        g_seginfo[n0 + 0] = make_int4(cex,                c0, o0, __float_as_int(s0));
        g_seginfo[n0 + 1] = make_int4(cex + c0,           c1, o1, __float_as_int(s1));
        g_seginfo[n0 + 2] = make_int4(cex + c0 + c1,      c2, o2, __float_as_int(s2));
        g_seginfo[n0 + 3] = make_int4(cex + c0 + c1 + c2, c3, o3, __float_as_int(s3));
    }
    if (lane == 0) g_btot[b] = ctot;
}

// ---------------------------------------------------------------------------
// Kernel 2: scatter metadata DIRECTLY into output-row order.
//   meta2[b_out*TX + t] = {src_row, lam}  for valid rows (t < rows)
//   meta2[b_out*TX + t] = {-1, 0}         for padding   (t in [rows, TX))
// Prologue is now PER-WARP: each warp loads g_btot[lane] (one 128B L2 line,
// broadcast), shfl-scans it, extracts its batch base + rows. No smem, no
// __syncthreads - every warp becomes runnable one L2 round-trip after the
// PDL gridsync, independent of its block siblings.
// ---------------------------------------------------------------------------
__global__ void __launch_bounds__(256) k_rowmeta() {
    cudaTriggerProgrammaticLaunchCompletion();   // let gather start dispatch

    const int tid = threadIdx.x;
    const int lane = tid & 31;
    const int n = blockIdx.x * 8 + (tid >> 5);   // this warp's segment
    const int bsrc = n / NSEG;                   // source batch (warp-uniform)

    cudaGridDependencySynchronize();             // wait: k_seg outputs visible

    // per-warp cross-batch scan: lane k carries batch k's total
    int gtot;
    const int gex = warp_excl(g_btot[lane], lane, gtot);
    const int rows = gtot / BB;
    const int bbase = __shfl_sync(0xffffffffu, gex, bsrc);  // base of batch bsrc

    const int4 si = g_seginfo[n];        // {local_base, cnt, off, scale_bits}
    const int cnt = si.y;
    if (cnt > 0 && rows > 0) {
        const int base  = bbase + si.x;           // absolute compacted base
        const int off   = si.z;
        const float scale = __int_as_float(si.w);
        const int bTX   = bsrc * TX;              // SOURCE batch row base

        for (int s = lane; s < cnt; s += 32) {    // cnt <= 64 -> <= 2 iters
            const float v  = __fdiv_rn((float)s, scale);
            const float fl = floorf(v);
            const float lam = v - fl;
            int i = (int)fl + off;                // exact small ints
            if (i > TX - 2) i = TX - 2;
            if (i < 0) i = 0;

            const int p = base + s;
            const int b_out = p / rows;           // output batch of position p
            const int t = p - b_out * rows;
            if (t < TX && b_out < BB)             // rows>TX or tail overflow
                g_meta2[b_out * TX + t] = make_int2(bTX + i, __float_as_int(lam));
        }
    }

    // ---- padding fill: grid-stride over the complement region ----
    const int padh = (rows < TX) ? (TX - rows) : 0;   // padding per batch
    const int padtot = BB * padh;
    for (int j = blockIdx.x * 256 + tid; j < padtot; j += (NTOT / 8) * 256) {
        const int b_out = j / padh;
        const int t = rows + (j - b_out * padh);
        g_meta2[b_out * TX + t] = make_int2(-1, 0);
    }
}

// ---------------------------------------------------------------------------
// Kernel 3: flat gather, ILP=2 (the R12 winner, unchanged). Index math runs
// BEFORE the PDL gridsync so it overlaps k_rowmeta's tail.
// ---------------------------------------------------------------------------
__global__ void __launch_bounds__(256) k_gather(const float* __restrict__ x,
                                                float* __restrict__ out) {
    const int g0 = blockIdx.x * 512 + threadIdx.x;   // two quads: g0, g0+256
    const int g1 = g0 + 256;

    const int row0 = g0 / D4, d40 = g0 - row0 * D4;
    const int row1 = g1 / D4, d41 = g1 - row1 * D4;

    cudaGridDependencySynchronize();             // wait: g_meta2 visible

    const int2 m0 = g_meta2[row0];                    // independent loads
    const int2 m1 = g_meta2[row1];

    const float4* __restrict__ x4 = (const float4*)x;
    float4 r0 = make_float4(0.f, 0.f, 0.f, 0.f);
    float4 r1 = make_float4(0.f, 0.f, 0.f, 0.f);

    if (m0.x >= 0) {
        const int sb = m0.x * D4 + d40;
        const float4 a = x4[sb];
        const float4 c = x4[sb + D4];
        const float lam = __int_as_float(m0.y), om = 1.0f - lam;
        r0.x = om * a.x + lam * c.x;  r0.y = om * a.y + lam * c.y;
        r0.z = om * a.z + lam * c.z;  r0.w = om * a.w + lam * c.w;
    }
    if (m1.x >= 0) {
        const int sb = m1.x * D4 + d41;
        const float4 a = x4[sb];
        const float4 c = x4[sb + D4];
        const float lam = __int_as_float(m1.y), om = 1.0f - lam;
        r1.x = om * a.x + lam * c.x;  r1.y = om * a.y + lam * c.y;
        r1.z = om * a.z + lam * c.z;  r1.w = om * a.w + lam * c.w;
    }

    float4* __restrict__ o4 = (float4*)out;
    o4[g0] = r0;
    o4[g1] = r1;
}

// ---------------------------------------------------------------------------
extern "C" void kernel_launch(void* const* d_in, const int* in_sizes, int n_in,
                              void* d_out, int out_size) {
    const float* x           = (const float*)d_in[0];  // (32, 2560, 80) f32
    const int*   len_seq     = (const int*)d_in[1];    // (32,) i32
    const float* scales_u    = (const float*)d_in[2];  // (3456,) f32
    const int*   len_seg_raw = (const int*)d_in[3];    // (3456,) i32
    float*       out         = (float*)d_out;          // (32, 2560, 80) f32

    // node 1: plain launch
    k_seg<<<BB, 32>>>(len_seq, scales_u, len_seg_raw);

    // PDL attribute: dependent grid may begin dispatch when producer triggers
    cudaLaunchAttribute attr[1];
    attr[0].id = cudaLaunchAttributeProgrammaticStreamSerialization;
    attr[0].val.programmaticStreamSerializationAllowed = 1;

    // node 2: k_rowmeta (PDL consumer of k_seg, producer for k_gather)
    {
        cudaLaunchConfig_t cfg = {};
        cfg.gridDim = dim3(NTOT / 8);
        cfg.blockDim = dim3(256);
        cfg.dynamicSmemBytes = 0;
        cfg.stream = 0;                 // legacy default stream (same as <<<>>>)
        cfg.attrs = attr;
        cfg.numAttrs = 1;
        cudaLaunchKernelEx(&cfg, k_rowmeta);
    }

    // node 3: k_gather (PDL consumer of k_rowmeta)
    {
        cudaLaunchConfig_t cfg = {};
        cfg.gridDim = dim3((BB * TX * D4) / 512);
        cfg.blockDim = dim3(256);
        cfg.dynamicSmemBytes = 0;
        cfg.stream = 0;
        cfg.attrs = attr;
        cfg.numAttrs = 1;
        cudaLaunchKernelEx(&cfg, k_gather, x, out);
    }
}

// round 16
// speedup vs baseline: 1.1775x; 1.0200x over previous
#include <cuda_runtime.h>

// Problem constants (fixed by reference hparams)
#define BB     32          // batch
#define NSEG   108         // MAX_NUM_SEG
#define NTOT   3456        // BB*NSEG
#define SS     64          // candidates per segment
#define TX     2560        // MAX_LEN_PAD
#define D4     20          // feature dim / 4 (float4 units)
#define MINSEG 19
#define OUTROWS (BB * TX)  // 81920 output rows
#define NQUAD  (OUTROWS * D4)   // 1,638,400 output float4s
#define NCHUNK (NQUAD / 512)    // 3200 chunks of 512 float4s
#define PGRID  1184             // persistent gather grid: 148 SMs x 8 blocks

// Scratch (no allocations allowed -> __device__ globals)
__device__ int4 g_seginfo[NTOT];    // {local_base, cnt, off, scale_bits}
__device__ int  g_btot[BB];         // per-batch count totals
__device__ int2 g_meta2[OUTROWS];   // per OUTPUT row: {src_row, lam} or {-1,0}

// ---------------------------------------------------------------------------
// shfl exclusive warp scan; returns exclusive prefix, sets warp total
// ---------------------------------------------------------------------------
__device__ __forceinline__ int warp_excl(int v, int lane, int& tot) {
    int x = v;
#pragma unroll
    for (int o = 1; o < 32; o <<= 1) {
        int y = __shfl_up_sync(0xffffffffu, x, o);
        if (lane >= o) x += y;
    }
    tot = __shfl_sync(0xffffffffu, x, 31);
    return x - v;
}

// Masked count for one segment: #{ s in [0,64) : floor(rn(s/scale)) < L }.
// Estimate seed + exact __fdiv_rn verification -> bit-exact vs reference.
__device__ __forceinline__ int seg_cnt(int len, int lseq, int off, float scale) {
    const int L = min(len - 1, lseq - 1 - off);
    if (L <= 0) return 0;
    const float Lf = (float)L;
    int s = (int)(Lf * scale);             // seed near the boundary
    if (s > 63) s = 63;
    while (s > 0 && !(floorf(__fdiv_rn((float)s, scale)) < Lf)) s--;
    while (s < 63 && (floorf(__fdiv_rn((float)(s + 1), scale)) < Lf)) s++;
    return s + 1;                          // cond(0) true since L>0
}

// ---------------------------------------------------------------------------
// Kernel 1: one WARP per batch (32 blocks x 32 threads), zero barriers.
// Triggers PDL completion at entry so k_rowmeta's dispatch overlaps this body.
// ---------------------------------------------------------------------------
__global__ void __launch_bounds__(32) k_seg(const int* __restrict__ len_seq,
                                            const float* __restrict__ scales_u,
                                            const int* __restrict__ len_seg_raw) {
    cudaTriggerProgrammaticLaunchCompletion();   // let consumers start dispatch

    const int b = blockIdx.x;
    const int lane = threadIdx.x;
    const bool act = lane < NSEG / 4;      // 27 active lanes

    int4 lr = make_int4(-MINSEG, -MINSEG, -MINSEG, -MINSEG);
    float4 sc = make_float4(0.5f, 0.5f, 0.5f, 0.5f);
    const int vidx = b * (NSEG / 4) + lane;
    if (act) {
        lr = ((const int4*)len_seg_raw)[vidx];
        sc = ((const float4*)scales_u)[vidx];
    }
    const int lseq = len_seq[b];

    const int l0 = lr.x + MINSEG, l1 = lr.y + MINSEG;
    const int l2 = lr.z + MINSEG, l3 = lr.w + MINSEG;
    const float s0 = sc.x + 0.5f, s1 = sc.y + 0.5f;
    const float s2 = sc.z + 0.5f, s3 = sc.w + 0.5f;

    // scan #1: len_seg -> offsets
    int tot;
    const int ex = warp_excl(l0 + l1 + l2 + l3, lane, tot);
    const int o0 = ex, o1 = ex + l0, o2 = o1 + l1, o3 = o2 + l2;

    // counts (ILP across 4 segments)
    const int c0 = seg_cnt(l0, lseq, o0, s0);
    const int c1 = seg_cnt(l1, lseq, o1, s1);
    const int c2 = seg_cnt(l2, lseq, o2, s2);
    const int c3 = seg_cnt(l3, lseq, o3, s3);

    // scan #2: counts -> local bases + batch total
    int ctot;
    const int cex = warp_excl(c0 + c1 + c2 + c3, lane, ctot);

    if (act) {
        const int n0 = b * NSEG + lane * 4;
        g_seginfo[n0 + 0] = make_int4(cex,                c0, o0, __float_as_int(s0));
        g_seginfo[n0 + 1] = make_int4(cex + c0,           c1, o1, __float_as_int(s1));
        g_seginfo[n0 + 2] = make_int4(cex + c0 + c1,      c2, o2, __float_as_int(s2));
        g_seginfo[n0 + 3] = make_int4(cex + c0 + c1 + c2, c3, o3, __float_as_int(s3));
    }
    if (lane == 0) g_btot[b] = ctot;
}

// ---------------------------------------------------------------------------
// Kernel 2: scatter metadata DIRECTLY into output-row order.
//   meta2[b_out*TX + t] = {src_row, lam}  for valid rows (t < rows)
//   meta2[b_out*TX + t] = {-1, 0}         for padding   (t in [rows, TX))
// Per-warp prologue: each warp loads g_btot[lane] (one 128B L2 line),
// shfl-scans it, extracts its batch base + rows. No smem, no barriers.
// ---------------------------------------------------------------------------
__global__ void __launch_bounds__(256) k_rowmeta() {
    cudaTriggerProgrammaticLaunchCompletion();   // let gather start dispatch

    const int tid = threadIdx.x;
    const int lane = tid & 31;
    const int n = blockIdx.x * 8 + (tid >> 5);   // this warp's segment
    const int bsrc = n / NSEG;                   // source batch (warp-uniform)

    cudaGridDependencySynchronize();             // wait: k_seg outputs visible

    // per-warp cross-batch scan: lane k carries batch k's total
    int gtot;
    const int gex = warp_excl(g_btot[lane], lane, gtot);
    const int rows = gtot / BB;
    const int bbase = __shfl_sync(0xffffffffu, gex, bsrc);  // base of batch bsrc

    const int4 si = g_seginfo[n];        // {local_base, cnt, off, scale_bits}
    const int cnt = si.y;
    if (cnt > 0 && rows > 0) {
        const int base  = bbase + si.x;           // absolute compacted base
        const int off   = si.z;
        const float scale = __int_as_float(si.w);
        const int bTX   = bsrc * TX;              // SOURCE batch row base

        for (int s = lane; s < cnt; s += 32) {    // cnt <= 64 -> <= 2 iters
            const float v  = __fdiv_rn((float)s, scale);
            const float fl = floorf(v);
            const float lam = v - fl;
            int i = (int)fl + off;                // exact small ints
            if (i > TX - 2) i = TX - 2;
            if (i < 0) i = 0;

            const int p = base + s;
            const int b_out = p / rows;           // output batch of position p
            const int t = p - b_out * rows;
            if (t < TX && b_out < BB)             // rows>TX or tail overflow
                g_meta2[b_out * TX + t] = make_int2(bTX + i, __float_as_int(lam));
        }
    }

    // ---- padding fill: grid-stride over the complement region ----
    const int padh = (rows < TX) ? (TX - rows) : 0;   // padding per batch
    const int padtot = BB * padh;
    for (int j = blockIdx.x * 256 + tid; j < padtot; j += (NTOT / 8) * 256) {
        const int b_out = j / padh;
        const int t = rows + (j - b_out * padh);
        g_meta2[b_out * TX + t] = make_int2(-1, 0);
    }
}

// ---------------------------------------------------------------------------
// Kernel 3: PERSISTENT flat gather, ILP=2 per chunk. Exactly one wave
// (1184 blocks = 148 SMs x 8 resident 256-thread blocks); each block
// grid-strides over 512-float4 chunks. No 2nd/3rd wave launch/drain;
// consecutive iterations pipeline loads within each warp.
// ---------------------------------------------------------------------------
__global__ void __launch_bounds__(256) k_gather(const float* __restrict__ x,
                                                float* __restrict__ out) {
    const int tid = threadIdx.x;

    cudaGridDependencySynchronize();             // wait: g_meta2 visible

    const float4* __restrict__ x4 = (const float4*)x;
    float4* __restrict__ o4 = (float4*)out;

    for (int chunk = blockIdx.x; chunk < NCHUNK; chunk += PGRID) {
        const int g0 = chunk * 512 + tid;        // two quads: g0, g0+256
        const int g1 = g0 + 256;

        const int row0 = g0 / D4, d40 = g0 - row0 * D4;
        const int row1 = g1 / D4, d41 = g1 - row1 * D4;

        const int2 m0 = g_meta2[row0];           // independent loads
        const int2 m1 = g_meta2[row1];

        float4 r0 = make_float4(0.f, 0.f, 0.f, 0.f);
        float4 r1 = make_float4(0.f, 0.f, 0.f, 0.f);

        if (m0.x >= 0) {
            const int sb = m0.x * D4 + d40;
            const float4 a = x4[sb];
            const float4 c = x4[sb + D4];
            const float lam = __int_as_float(m0.y), om = 1.0f - lam;
            r0.x = om * a.x + lam * c.x;  r0.y = om * a.y + lam * c.y;
            r0.z = om * a.z + lam * c.z;  r0.w = om * a.w + lam * c.w;
        }
        if (m1.x >= 0) {
            const int sb = m1.x * D4 + d41;
            const float4 a = x4[sb];
            const float4 c = x4[sb + D4];
            const float lam = __int_as_float(m1.y), om = 1.0f - lam;
            r1.x = om * a.x + lam * c.x;  r1.y = om * a.y + lam * c.y;
            r1.z = om * a.z + lam * c.z;  r1.w = om * a.w + lam * c.w;
        }

        o4[g0] = r0;
        o4[g1] = r1;
    }
}

// ---------------------------------------------------------------------------
extern "C" void kernel_launch(void* const* d_in, const int* in_sizes, int n_in,
                              void* d_out, int out_size) {
    const float* x           = (const float*)d_in[0];  // (32, 2560, 80) f32
    const int*   len_seq     = (const int*)d_in[1];    // (32,) i32
    const float* scales_u    = (const float*)d_in[2];  // (3456,) f32
    const int*   len_seg_raw = (const int*)d_in[3];    // (3456,) i32
    float*       out         = (float*)d_out;          // (32, 2560, 80) f32

    // node 1: plain launch
    k_seg<<<BB, 32>>>(len_seq, scales_u, len_seg_raw);

    // PDL attribute: dependent grid may begin dispatch when producer triggers
    cudaLaunchAttribute attr[1];
    attr[0].id = cudaLaunchAttributeProgrammaticStreamSerialization;
    attr[0].val.programmaticStreamSerializationAllowed = 1;

    // node 2: k_rowmeta (PDL consumer of k_seg, producer for k_gather)
    {
        cudaLaunchConfig_t cfg = {};
        cfg.gridDim = dim3(NTOT / 8);
        cfg.blockDim = dim3(256);
        cfg.dynamicSmemBytes = 0;
        cfg.stream = 0;                 // legacy default stream (same as <<<>>>)
        cfg.attrs = attr;
        cfg.numAttrs = 1;
        cudaLaunchKernelEx(&cfg, k_rowmeta);
    }

    // node 3: k_gather (PDL consumer of k_rowmeta), persistent single wave
    {
        cudaLaunchConfig_t cfg = {};
        cfg.gridDim = dim3(PGRID);
        cfg.blockDim = dim3(256);
        cfg.dynamicSmemBytes = 0;
        cfg.stream = 0;
        cfg.attrs = attr;
        cfg.numAttrs = 1;
        cudaLaunchKernelEx(&cfg, k_gather, x, out);
    }
}